// round 12
// baseline (speedup 1.0000x reference)
#include <cuda_runtime.h>
#include <cuda.h>

#define NB 32
#define NT 8192
#define NC 1024
#define NH 16
#define SCALE 0.03125f   // 1024^-0.5

#define TILE_R 256
#define KC 32
#define NCH (NC / KC)            // 32 chunks
#define XBUF 8192                // floats per TMA stage buffer (256*32)
#define XBYTES 32768             // bytes per TMA chunk

// fallback (R9) staging geometry
#define XSTR 36

// ---- scratch ----
__device__ float g_scores[(size_t)NB * NT * NH];
__device__ float g_Z[NB * NH];
__device__ float g_pooled[NB * NC];
__device__ float g_qT[NC * NH];          // qT[c][h]
__device__ CUtensorMap g_tmap;           // TMA descriptor in GLOBAL memory

__device__ __forceinline__ void ffma2(unsigned long long& d,
                                      unsigned long long a,
                                      unsigned long long b) {
    asm("fma.rn.f32x2 %0, %1, %2, %0;" : "+l"(d) : "l"(a), "l"(b));
}
__device__ __forceinline__ unsigned long long add2(unsigned long long a,
                                                   unsigned long long b) {
    unsigned long long r;
    asm("add.rn.f32x2 %0, %1, %2;" : "=l"(r) : "l"(a), "l"(b));
    return r;
}
__device__ __forceinline__ unsigned long long pack2(float v) {
    unsigned long long r;
    asm("mov.b64 %0, {%1, %1};" : "=l"(r) : "f"(v));
    return r;
}
__device__ __forceinline__ float lo2(unsigned long long a) { return __uint_as_float((unsigned)a); }
__device__ __forceinline__ float hi2(unsigned long long a) { return __uint_as_float((unsigned)(a >> 32)); }

__device__ __forceinline__ unsigned smem_u32(const void* p) {
    return (unsigned)__cvta_generic_to_shared(p);
}
__device__ __forceinline__ void mbar_init(unsigned mbar, unsigned cnt) {
    asm volatile("mbarrier.init.shared.b64 [%0], %1;" :: "r"(mbar), "r"(cnt) : "memory");
}
__device__ __forceinline__ void mbar_expect_tx(unsigned mbar, unsigned bytes) {
    asm volatile("mbarrier.arrive.expect_tx.shared.b64 _, [%0], %1;"
                 :: "r"(mbar), "r"(bytes) : "memory");
}
__device__ __forceinline__ void mbar_wait(unsigned mbar, unsigned parity) {
    asm volatile(
        "{\n\t.reg .pred P;\n\t"
        "W_%=:\n\t"
        "mbarrier.try_wait.parity.acquire.cta.shared::cta.b64 P, [%0], %1;\n\t"
        "@!P bra W_%=;\n\t}"
        :: "r"(mbar), "r"(parity) : "memory");
}
__device__ __forceinline__ void tma_2d(unsigned smem_dst, const CUtensorMap* tmap,
                                       int cx, int cy, unsigned mbar) {
    asm volatile(
        "cp.async.bulk.tensor.2d.shared::cta.global.tile.mbarrier::complete_tx::bytes "
        "[%0], [%1, {%2, %3}], [%4];"
        :: "r"(smem_dst), "l"(tmap), "r"(cx), "r"(cy), "r"(mbar) : "memory");
}

// ============================================================
// K0: zero accumulators, build qT[c][h], publish tensormap to global.
// ============================================================
__global__ void k_zero(const float* __restrict__ q,
                       const __grid_constant__ CUtensorMap tm,
                       int have_tma) {
    int i = blockIdx.x * blockDim.x + threadIdx.x;
    if (i < NB * NC) g_pooled[i] = 0.0f;
    if (i < NB * NH) g_Z[i] = 0.0f;
    if (i < NC * NH) {
        int c = i >> 4, h = i & 15;
        g_qT[i] = q[h * NC + c];
    }
    if (have_tma && blockIdx.x == 0 && threadIdx.x < 32) {
        ((unsigned*)&g_tmap)[threadIdx.x] = ((const unsigned*)&tm)[threadIdx.x];
        __syncwarp();
        if (threadIdx.x == 0)
            asm volatile("fence.proxy.tensormap::generic.release.gpu;" ::: "memory");
    }
}

// ============================================================
// K1a (TMA path): scores GEMM, x via 2-stage TMA SW128 — no LDG/STS.
// 256 threads; thread = (warp, rl=lane>>2, chq=lane&3):
// rows rl+8*warp+64*m (m<4), channel-quarter chq, all 16 heads.
// Swizzled conflict-free LDS: physical 16B slot = logical ^ (row&7).
// ============================================================
__global__ void __launch_bounds__(256, 1)
k_scores_tma() {
    extern __shared__ char smraw[];
    float* base = (float*)((((size_t)smraw) + 1023) & ~(size_t)1023);
    float* qts = base;                   // 16*1024 floats (64 KB)
    float* xs  = base + NH * NC;         // 2 * 8192 floats (64 KB)
    __shared__ float zsh[NH];
    __shared__ __align__(8) unsigned long long mbar[2];

    const int b = blockIdx.y, tile = blockIdx.x, tid = threadIdx.x;
    const int warp = tid >> 5, lane = tid & 31;
    const int rl = lane >> 2, chq = lane & 3;
    const int p0 = chq ^ rl, p1 = (chq + 4) ^ rl;   // swizzled 16B slots
    const int rowbase = b * NT + tile * TILE_R;
    const CUtensorMap* tmp = &g_tmap;

    for (int i = tid; i < NC * NH / 4; i += 256)
        ((float4*)qts)[i] = ((const float4*)g_qT)[i];
    if (tid < NH) zsh[tid] = 0.0f;
    if (tid == 0) {
        mbar_init(smem_u32(&mbar[0]), 1);
        mbar_init(smem_u32(&mbar[1]), 1);
        asm volatile("fence.proxy.async.shared::cta;" ::: "memory");
        asm volatile("fence.proxy.tensormap::generic.acquire.gpu [%0], 128;"
                     :: "l"(tmp) : "memory");
    }
    __syncthreads();

    const unsigned mb[2] = { smem_u32(&mbar[0]), smem_u32(&mbar[1]) };
    const unsigned xsu = smem_u32(xs);

    if (tid == 0) {
        mbar_expect_tx(mb[0], XBYTES);
        tma_2d(xsu,          tmp, 0,  rowbase, mb[0]);
        mbar_expect_tx(mb[1], XBYTES);
        tma_2d(xsu + XBYTES, tmp, KC, rowbase, mb[1]);
    }

    unsigned long long acc[4][8];
    #pragma unroll
    for (int m = 0; m < 4; m++)
        #pragma unroll
        for (int h = 0; h < 8; h++) acc[m][h] = 0ull;

    for (int c = 0; c < NCH; c++) {
        const int stage = c & 1;
        mbar_wait(mb[stage], (c >> 1) & 1);
        const float* xb = xs + stage * XBUF;

        ulonglong2 xv[4][2];
        #pragma unroll
        for (int m = 0; m < 4; m++) {
            const float* rp = xb + (rl + 8 * warp + 64 * m) * KC;
            xv[m][0] = *(const ulonglong2*)(rp + p0 * 4);
            xv[m][1] = *(const ulonglong2*)(rp + p1 * 4);
        }

        const float* qb = qts + (size_t)c * KC * NH;
        #pragma unroll
        for (int half = 0; half < 2; half++) {
            #pragma unroll
            for (int i = 0; i < 4; i++) {
                const int ch = half * 16 + 4 * chq + i;
                const float* qr = qb + ch * NH;
                ulonglong2 q01 = *(const ulonglong2*)(qr);
                ulonglong2 q23 = *(const ulonglong2*)(qr + 4);
                ulonglong2 q45 = *(const ulonglong2*)(qr + 8);
                ulonglong2 q67 = *(const ulonglong2*)(qr + 12);
                #pragma unroll
                for (int m = 0; m < 4; m++) {
                    unsigned long long x2 =
                        pack2(((const float*)&xv[m][half])[i]);
                    ffma2(acc[m][0], x2, q01.x);
                    ffma2(acc[m][1], x2, q01.y);
                    ffma2(acc[m][2], x2, q23.x);
                    ffma2(acc[m][3], x2, q23.y);
                    ffma2(acc[m][4], x2, q45.x);
                    ffma2(acc[m][5], x2, q45.y);
                    ffma2(acc[m][6], x2, q67.x);
                    ffma2(acc[m][7], x2, q67.y);
                }
            }
        }
        __syncthreads();
        if (tid == 0 && c + 2 < NCH) {
            mbar_expect_tx(mb[stage], XBYTES);
            tma_2d(xsu + stage * XBYTES, tmp, (c + 2) * KC, rowbase, mb[stage]);
        }
    }

    #pragma unroll
    for (int st = 1; st <= 2; st <<= 1)
        #pragma unroll
        for (int m = 0; m < 4; m++)
            #pragma unroll
            for (int h = 0; h < 8; h++)
                acc[m][h] = add2(acc[m][h],
                                 __shfl_xor_sync(0xffffffffu, acc[m][h], st));

    float zacc[16];
    #pragma unroll
    for (int h = 0; h < 16; h++) zacc[h] = 0.0f;

    if (chq == 0) {
        #pragma unroll
        for (int m = 0; m < 4; m++) {
            const int rr = tile * TILE_R + rl + 8 * warp + 64 * m;
            float s[16];
            #pragma unroll
            for (int h = 0; h < 8; h++) {
                s[2 * h]     = lo2(acc[m][h]) * SCALE;
                s[2 * h + 1] = hi2(acc[m][h]) * SCALE;
            }
            float* dst = g_scores + ((size_t)b * NT + rr) * NH;
            *(float4*)(dst + 0)  = make_float4(s[0],  s[1],  s[2],  s[3]);
            *(float4*)(dst + 4)  = make_float4(s[4],  s[5],  s[6],  s[7]);
            *(float4*)(dst + 8)  = make_float4(s[8],  s[9],  s[10], s[11]);
            *(float4*)(dst + 12) = make_float4(s[12], s[13], s[14], s[15]);
            #pragma unroll
            for (int h = 0; h < 16; h++) zacc[h] += expf(s[h]);
        }
    }
    #pragma unroll
    for (int st = 4; st <= 16; st <<= 1)
        #pragma unroll
        for (int h = 0; h < 16; h++)
            zacc[h] += __shfl_xor_sync(0xffffffffu, zacc[h], st);
    if (lane == 0) {
        #pragma unroll
        for (int h = 0; h < 16; h++) atomicAdd(&zsh[h], zacc[h]);
    }
    __syncthreads();
    if (tid < NH) atomicAdd(&g_Z[b * NH + tid], zsh[tid]);
}

// ============================================================
// K1b (fallback, R9-proven): scores GEMM with LDG->STS staging.
// ============================================================
__global__ void __launch_bounds__(128, 2)
k_scores_fb(const float* __restrict__ x, const float* __restrict__ q) {
    extern __shared__ float sm[];
    float* qs = sm;                      // 64 KB
    float* xs = sm + NH * NC;            // 36 KB
    __shared__ float zsh[NH];

    const int b = blockIdx.y, tile = blockIdx.x, tid = threadIdx.x;
    const int rowg = tid & 63, headg = tid >> 6;
    const int crow = tid >> 3, ccol = (tid & 7) * 4;

    for (int i = tid; i < NH * NC / 4; i += 128)
        ((float4*)qs)[i] = ((const float4*)q)[i];
    if (tid < NH) zsh[tid] = 0.0f;

    const float* xb = x + ((size_t)(b * NT + tile * TILE_R)) * NC;

    float4 r[16];
#define LOADC(c)                                                            \
    _Pragma("unroll")                                                       \
    for (int g = 0; g < 16; g++)                                            \
        r[g] = *(const float4*)(xb + (size_t)(g * 16 + crow) * NC           \
                                + (c) * KC + ccol);
    LOADC(0);

    unsigned long long acc[4][8];
    #pragma unroll
    for (int m = 0; m < 4; m++)
        #pragma unroll
        for (int h = 0; h < 8; h++) acc[m][h] = 0ull;

    for (int c = 0; c < NCH; c++) {
        #pragma unroll
        for (int g = 0; g < 16; g++)
            *(float4*)(xs + (g * 16 + crow) * XSTR + ccol) = r[g];
        __syncthreads();

        if (c + 1 < NCH) { LOADC(c + 1); }

        const float* qc = qs + (size_t)headg * 8 * NC + c * KC;
        #pragma unroll
        for (int j = 0; j < 8; j++) {
            ulonglong2 xv[4];
            #pragma unroll
            for (int m = 0; m < 4; m++)
                xv[m] = *(const ulonglong2*)(xs + (rowg + 64 * m) * XSTR + 4 * j);
            #pragma unroll
            for (int h = 0; h < 8; h++) {
                ulonglong2 qv = *(const ulonglong2*)(qc + h * NC + 4 * j);
                #pragma unroll
                for (int m = 0; m < 4; m++) {
                    ffma2(acc[m][h], xv[m].x, qv.x);
                    ffma2(acc[m][h], xv[m].y, qv.y);
                }
            }
        }
        __syncthreads();
    }
#undef LOADC

    float zacc[8];
    #pragma unroll
    for (int h = 0; h < 8; h++) zacc[h] = 0.0f;
    #pragma unroll
    for (int m = 0; m < 4; m++) {
        int rr = tile * TILE_R + rowg + 64 * m;
        float s[8];
        #pragma unroll
        for (int h = 0; h < 8; h++) {
            s[h] = (lo2(acc[m][h]) + hi2(acc[m][h])) * SCALE;
            zacc[h] += expf(s[h]);
        }
        float* dst = g_scores + ((size_t)b * NT + rr) * NH + headg * 8;
        *(float4*)(dst + 0) = make_float4(s[0], s[1], s[2], s[3]);
        *(float4*)(dst + 4) = make_float4(s[4], s[5], s[6], s[7]);
    }
    #pragma unroll
    for (int h = 0; h < 8; h++) {
        float v = zacc[h];
        #pragma unroll
        for (int m2 = 16; m2 >= 1; m2 >>= 1)
            v += __shfl_xor_sync(0xffffffffu, v, m2);
        if ((tid & 31) == 0) atomicAdd(&zsh[headg * 8 + h], v);
    }
    __syncthreads();
    if (tid < NH) atomicAdd(&g_Z[b * NH + tid], zsh[tid]);
}

// ============================================================
// K2: pooled[b,c] += sum_t w[b,t]*x[b,t,c],  w = (1/16) sum_h exp(s)/Z_h
// ============================================================
__global__ void __launch_bounds__(256)
k_pool(const float* __restrict__ x) {
    __shared__ float ws[128];
    __shared__ float rz[16];
    const int b = blockIdx.y, tile = blockIdx.x, tid = threadIdx.x;

    if (tid < 16) rz[tid] = 1.0f / g_Z[b * NH + tid];
    __syncthreads();

    if (tid < 128) {
        const int r = tile * 128 + tid;
        const float4* sp = (const float4*)(g_scores + ((size_t)b * NT + r) * NH);
        float4 s0 = sp[0], s1 = sp[1], s2 = sp[2], s3 = sp[3];
        float w = expf(s0.x) * rz[0]  + expf(s0.y) * rz[1]
                + expf(s0.z) * rz[2]  + expf(s0.w) * rz[3]
                + expf(s1.x) * rz[4]  + expf(s1.y) * rz[5]
                + expf(s1.z) * rz[6]  + expf(s1.w) * rz[7]
                + expf(s2.x) * rz[8]  + expf(s2.y) * rz[9]
                + expf(s2.z) * rz[10] + expf(s2.w) * rz[11]
                + expf(s3.x) * rz[12] + expf(s3.y) * rz[13]
                + expf(s3.z) * rz[14] + expf(s3.w) * rz[15];
        ws[tid] = w * (1.0f / 16.0f);
    }
    __syncthreads();

    const int c = tid * 4;
    float4 a0 = make_float4(0.f, 0.f, 0.f, 0.f);
    float4 a1 = make_float4(0.f, 0.f, 0.f, 0.f);
    const float* xb = x + ((size_t)b * NT + tile * 128) * NC + c;
    #pragma unroll 4
    for (int r = 0; r < 128; r += 2) {
        float4 x0 = *(const float4*)(xb + (size_t)r * NC);
        float4 x1 = *(const float4*)(xb + (size_t)(r + 1) * NC);
        float w0 = ws[r], w1 = ws[r + 1];
        a0.x += w0 * x0.x; a0.y += w0 * x0.y; a0.z += w0 * x0.z; a0.w += w0 * x0.w;
        a1.x += w1 * x1.x; a1.y += w1 * x1.y; a1.z += w1 * x1.z; a1.w += w1 * x1.w;
    }
    float* pp = g_pooled + b * NC + c;
    atomicAdd(pp + 0, a0.x + a1.x);
    atomicAdd(pp + 1, a0.y + a1.y);
    atomicAdd(pp + 2, a0.z + a1.z);
    atomicAdd(pp + 3, a0.w + a1.w);
}

// ============================================================
// K3: out[b,j] = <pooled[b,:], W[j,:]> + bias[j]
// ============================================================
__global__ void __launch_bounds__(256)
k_proj(const float* __restrict__ w, const float* __restrict__ bias,
       float* __restrict__ out) {
    const int warp = threadIdx.x >> 5, lane = threadIdx.x & 31;
    const int j = blockIdx.x * 8 + warp;

    float4 wr[8];
    const float4* wp = (const float4*)(w + (size_t)j * NC);
    #pragma unroll
    for (int i = 0; i < 8; i++) wr[i] = wp[lane + 32 * i];
    const float bj = bias[j];

    const int b0 = blockIdx.y * 8;
    for (int b = b0; b < b0 + 8; b++) {
        const float4* pp = (const float4*)(g_pooled + b * NC);
        float acc = 0.0f;
        #pragma unroll
        for (int i = 0; i < 8; i++) {
            float4 pv = pp[lane + 32 * i];
            acc += pv.x * wr[i].x + pv.y * wr[i].y
                 + pv.z * wr[i].z + pv.w * wr[i].w;
        }
        #pragma unroll
        for (int m = 16; m >= 1; m >>= 1)
            acc += __shfl_xor_sync(0xffffffffu, acc, m);
        if (lane == 0) out[b * NC + j] = acc + bj;
    }
}

// ============================================================
extern "C" void kernel_launch(void* const* d_in, const int* in_sizes, int n_in,
                              void* d_out, int out_size) {
    const float* x  = (const float*)d_in[0];
    const float* q  = (const float*)d_in[1];
    const float* pw = (const float*)d_in[2];
    const float* pb = (const float*)d_in[3];
    float* out      = (float*)d_out;

    typedef CUresult (*EncodeFn)(
        CUtensorMap*, CUtensorMapDataType, cuuint32_t, void*,
        const cuuint64_t*, const cuuint64_t*, const cuuint32_t*,
        const cuuint32_t*, CUtensorMapInterleave, CUtensorMapSwizzle,
        CUtensorMapL2promotion, CUtensorMapFloatOOBfill);
    static EncodeFn enc = nullptr;
    static bool enc_tried = false;
    if (!enc_tried) {
        enc_tried = true;
        void* fp = nullptr;
        cudaDriverEntryPointQueryResult qr;
        if (cudaGetDriverEntryPoint("cuTensorMapEncodeTiled", &fp,
                                    cudaEnableDefault, &qr) == cudaSuccess &&
            qr == cudaDriverEntryPointSuccess)
            enc = (EncodeFn)fp;
    }

    static CUtensorMap h_tmap;   // persists for capture replays
    int have_tma = 0;
    if (enc) {
        cuuint64_t dims[2]    = { (cuuint64_t)NC, (cuuint64_t)NB * NT };
        cuuint64_t strides[1] = { (cuuint64_t)NC * sizeof(float) };
        cuuint32_t box[2]     = { KC, TILE_R };
        cuuint32_t estr[2]    = { 1, 1 };
        CUresult r = enc(&h_tmap, CU_TENSOR_MAP_DATA_TYPE_FLOAT32, 2, (void*)x,
                         dims, strides, box, estr,
                         CU_TENSOR_MAP_INTERLEAVE_NONE, CU_TENSOR_MAP_SWIZZLE_128B,
                         CU_TENSOR_MAP_L2_PROMOTION_L2_128B,
                         CU_TENSOR_MAP_FLOAT_OOB_FILL_NONE);
        have_tma = (r == CUDA_SUCCESS) ? 1 : 0;
    }

    const int smem_tma = (NH * NC + 2 * XBUF) * (int)sizeof(float) + 1024;
    const int smem_fb  = (NH * NC + TILE_R * XSTR) * (int)sizeof(float);
    cudaFuncSetAttribute(k_scores_tma, cudaFuncAttributeMaxDynamicSharedMemorySize, smem_tma);
    cudaFuncSetAttribute(k_scores_fb,  cudaFuncAttributeMaxDynamicSharedMemorySize, smem_fb);

    k_zero<<<128, 256>>>(q, h_tmap, have_tma);
    if (have_tma)
        k_scores_tma<<<dim3(NT / TILE_R, NB), 256, smem_tma>>>();
    else
        k_scores_fb<<<dim3(NT / TILE_R, NB), 128, smem_fb>>>(x, q);
    k_pool<<<dim3(64, NB), 256>>>(x);
    k_proj<<<dim3(128, 4), 256>>>(pw, pb, out);
}

// round 15
// speedup vs baseline: 1.3805x; 1.3805x over previous
#include <cuda_runtime.h>
#include <cuda_fp16.h>

#define NB 32
#define NT 8192
#define NC 1024
#define NH 16
#define SCALE 0.03125f   // 1024^-0.5

#define TILE_R 256
#define KC 16
#define XSTR 20                  // 16 + 4 pad: conflict-free phases
#define NCH (NC / KC)            // 64 chunks

// ---- scratch ----
__device__ __align__(16) __half g_scoresh[(size_t)NB * NT * NH];  // 33.5 MB
__device__ float g_Z[NB * NH];
__device__ float g_pooled[NB * NC];

union HPack { __half2 h2[4]; uint4 u; };

__device__ __forceinline__ void ffma2(unsigned long long& d,
                                      unsigned long long a,
                                      unsigned long long b) {
    asm("fma.rn.f32x2 %0, %1, %2, %0;" : "+l"(d) : "l"(a), "l"(b));
}
__device__ __forceinline__ float lo2(unsigned long long a) { return __uint_as_float((unsigned)a); }
__device__ __forceinline__ float hi2(unsigned long long a) { return __uint_as_float((unsigned)(a >> 32)); }

// ============================================================
__global__ void k_zero() {
    int i = blockIdx.x * blockDim.x + threadIdx.x;
    if (i < NB * NC) g_pooled[i] = 0.0f;
    if (i < NB * NH) g_Z[i] = 0.0f;
}

// ============================================================
// K1: scores GEMM — EXACT R4 structure (proven 470.7us), fp16 output.
// CTA: 256 rows x 16 heads, 128 threads (64 rowg x 2 headg),
// thread tile 4 rows x 8 heads, f32x2 accums over channel parity.
// Single x buffer; LDGs for chunk c+1 overlap compute on chunk c.
// ============================================================
__global__ void __launch_bounds__(128, 2)
k_scores(const float* __restrict__ x, const float* __restrict__ q) {
    extern __shared__ float sm[];
    float* qs = sm;                      // 16*1024 floats (64 KB)
    float* xs = sm + NH * NC;            // 256*20 floats  (20 KB)
    __shared__ float zsh[NH];

    const int b = blockIdx.y, tile = blockIdx.x, tid = threadIdx.x;
    const int rowg = tid & 63, headg = tid >> 6;      // 64 x 2
    const int crow = tid >> 2, ccol = (tid & 3) * 4;  // copy: 4 lanes/row

    for (int i = tid; i < NH * NC / 4; i += 128)
        ((float4*)qs)[i] = ((const float4*)q)[i];
    if (tid < NH) zsh[tid] = 0.0f;

    const float* xb = x + ((size_t)(b * NT + tile * TILE_R)) * NC;

    float4 r[8];
#define LOADC(c)                                                            \
    _Pragma("unroll")                                                       \
    for (int g = 0; g < 8; g++)                                             \
        r[g] = *(const float4*)(xb + (size_t)(g * 32 + crow) * NC           \
                                + (c) * KC + ccol);

    LOADC(0);

    unsigned long long acc[4][8];
    #pragma unroll
    for (int m = 0; m < 4; m++)
        #pragma unroll
        for (int h = 0; h < 8; h++) acc[m][h] = 0ull;

    for (int c = 0; c < NCH; c++) {
        #pragma unroll
        for (int g = 0; g < 8; g++)
            *(float4*)(xs + (g * 32 + crow) * XSTR + ccol) = r[g];
        __syncthreads();

        if (c + 1 < NCH) { LOADC(c + 1); }   // LDGs overlap compute

        const float* qc = qs + (size_t)headg * 8 * NC + c * KC;
        #pragma unroll
        for (int j = 0; j < 4; j++) {        // 4 channels per step
            ulonglong2 xv[4];
            #pragma unroll
            for (int m = 0; m < 4; m++)
                xv[m] = *(const ulonglong2*)(xs + (rowg + 64 * m) * XSTR + 4 * j);
            #pragma unroll
            for (int h = 0; h < 8; h++) {
                ulonglong2 qv = *(const ulonglong2*)(qc + h * NC + 4 * j); // broadcast
                #pragma unroll
                for (int m = 0; m < 4; m++) {
                    ffma2(acc[m][h], xv[m].x, qv.x);
                    ffma2(acc[m][h], xv[m].y, qv.y);
                }
            }
        }
        __syncthreads();   // readers done before next STS
    }
#undef LOADC

    float zacc[8];
    #pragma unroll
    for (int h = 0; h < 8; h++) zacc[h] = 0.0f;

    #pragma unroll
    for (int m = 0; m < 4; m++) {
        int rr = tile * TILE_R + rowg + 64 * m;
        float s[8];
        #pragma unroll
        for (int h = 0; h < 8; h++) {
            s[h] = (lo2(acc[m][h]) + hi2(acc[m][h])) * SCALE;
            zacc[h] += expf(s[h]);
        }
        HPack pk;
        pk.h2[0] = __floats2half2_rn(s[0], s[1]);
        pk.h2[1] = __floats2half2_rn(s[2], s[3]);
        pk.h2[2] = __floats2half2_rn(s[4], s[5]);
        pk.h2[3] = __floats2half2_rn(s[6], s[7]);
        *(uint4*)(g_scoresh + ((size_t)b * NT + rr) * NH + headg * 8) = pk.u;
    }
    #pragma unroll
    for (int h = 0; h < 8; h++) {
        float v = zacc[h];
        #pragma unroll
        for (int m2 = 16; m2 >= 1; m2 >>= 1)
            v += __shfl_xor_sync(0xffffffffu, v, m2);
        if ((tid & 31) == 0) atomicAdd(&zsh[headg * 8 + h], v);
    }
    __syncthreads();
    if (tid < NH) atomicAdd(&g_Z[b * NH + tid], zsh[tid]);
}

// ============================================================
// K2: pooled[b,c] += sum_t w[b,t]*x[b,t,c],  w = (1/16) sum_h exp(s)/Z_h
// scores read fp16 (half the score traffic of R4).
// ============================================================
__global__ void __launch_bounds__(256)
k_pool(const float* __restrict__ x) {
    __shared__ float ws[128];
    __shared__ float rz[16];
    const int b = blockIdx.y, tile = blockIdx.x, tid = threadIdx.x;

    if (tid < 16) rz[tid] = 1.0f / g_Z[b * NH + tid];
    __syncthreads();

    if (tid < 128) {
        const int r = tile * 128 + tid;
        HPack pk;
        pk.u = *(const uint4*)(g_scoresh + ((size_t)b * NT + r) * NH);
        float w = 0.0f;
        #pragma unroll
        for (int k = 0; k < 4; k++) {
            float2 f = __half22float2(pk.h2[k]);
            w += expf(f.x) * rz[2 * k] + expf(f.y) * rz[2 * k + 1];
        }
        HPack pk2;
        pk2.u = *(const uint4*)(g_scoresh + ((size_t)b * NT + r) * NH + 8);
        #pragma unroll
        for (int k = 0; k < 4; k++) {
            float2 f = __half22float2(pk2.h2[k]);
            w += expf(f.x) * rz[8 + 2 * k] + expf(f.y) * rz[8 + 2 * k + 1];
        }
        ws[tid] = w * (1.0f / 16.0f);
    }
    __syncthreads();

    const int c = tid * 4;
    float4 a0 = make_float4(0.f, 0.f, 0.f, 0.f);
    float4 a1 = make_float4(0.f, 0.f, 0.f, 0.f);
    const float* xb = x + ((size_t)b * NT + tile * 128) * NC + c;
    #pragma unroll 4
    for (int r = 0; r < 128; r += 2) {
        float4 x0 = *(const float4*)(xb + (size_t)r * NC);
        float4 x1 = *(const float4*)(xb + (size_t)(r + 1) * NC);
        float w0 = ws[r], w1 = ws[r + 1];
        a0.x += w0 * x0.x; a0.y += w0 * x0.y; a0.z += w0 * x0.z; a0.w += w0 * x0.w;
        a1.x += w1 * x1.x; a1.y += w1 * x1.y; a1.z += w1 * x1.z; a1.w += w1 * x1.w;
    }
    float* pp = g_pooled + b * NC + c;
    atomicAdd(pp + 0, a0.x + a1.x);
    atomicAdd(pp + 1, a0.y + a1.y);
    atomicAdd(pp + 2, a0.z + a1.z);
    atomicAdd(pp + 3, a0.w + a1.w);
}

// ============================================================
// K3: out[b,j] = <pooled[b,:], W[j,:]> + bias[j]
// ============================================================
__global__ void __launch_bounds__(256)
k_proj(const float* __restrict__ w, const float* __restrict__ bias,
       float* __restrict__ out) {
    const int warp = threadIdx.x >> 5, lane = threadIdx.x & 31;
    const int j = blockIdx.x * 8 + warp;

    float4 wr[8];
    const float4* wp = (const float4*)(w + (size_t)j * NC);
    #pragma unroll
    for (int i = 0; i < 8; i++) wr[i] = wp[lane + 32 * i];
    const float bj = bias[j];

    const int b0 = blockIdx.y * 8;
    for (int b = b0; b < b0 + 8; b++) {
        const float4* pp = (const float4*)(g_pooled + b * NC);
        float acc = 0.0f;
        #pragma unroll
        for (int i = 0; i < 8; i++) {
            float4 pv = pp[lane + 32 * i];
            acc += pv.x * wr[i].x + pv.y * wr[i].y
                 + pv.z * wr[i].z + pv.w * wr[i].w;
        }
        #pragma unroll
        for (int m = 16; m >= 1; m >>= 1)
            acc += __shfl_xor_sync(0xffffffffu, acc, m);
        if (lane == 0) out[b * NC + j] = acc + bj;
    }
}

// ============================================================
extern "C" void kernel_launch(void* const* d_in, const int* in_sizes, int n_in,
                              void* d_out, int out_size) {
    const float* x  = (const float*)d_in[0];
    const float* q  = (const float*)d_in[1];
    const float* pw = (const float*)d_in[2];
    const float* pb = (const float*)d_in[3];
    float* out      = (float*)d_out;

    const int smem = (NH * NC + TILE_R * XSTR) * (int)sizeof(float);  // 84 KB
    cudaFuncSetAttribute(k_scores, cudaFuncAttributeMaxDynamicSharedMemorySize, smem);

    k_zero<<<128, 256>>>();
    k_scores<<<dim3(NT / TILE_R, NB), 128, smem>>>(x, q);
    k_pool<<<dim3(64, NB), 256>>>(x);
    k_proj<<<dim3(128, 4), 256>>>(pw, pb, out);
}

// round 16
// speedup vs baseline: 1.6004x; 1.1593x over previous
#include <cuda_runtime.h>
#include <cuda_fp16.h>

#define NB 32
#define NT 8192
#define NC 1024
#define NH 16
#define SCALE 0.03125f   // 1024^-0.5

#define TILE_R 256
#define KC 16
#define XSTR 20                  // 16 + 4 pad: conflict-free phases
#define NCH (NC / KC)            // 64 chunks

// ---- scratch ----
__device__ __align__(16) __half g_scoresh[(size_t)NB * NT * NH];  // 33.5 MB
__device__ float g_Z[NB * NH];
__device__ float g_pooled[NB * NC];

union HPack { __half2 h2[4]; uint4 u; };

__device__ __forceinline__ void ffma2(unsigned long long& d,
                                      unsigned long long a,
                                      unsigned long long b) {
    asm("fma.rn.f32x2 %0, %1, %2, %0;" : "+l"(d) : "l"(a), "l"(b));
}
__device__ __forceinline__ float lo2(unsigned long long a) { return __uint_as_float((unsigned)a); }
__device__ __forceinline__ float hi2(unsigned long long a) { return __uint_as_float((unsigned)(a >> 32)); }

// ============================================================
__global__ void k_zero() {
    int i = blockIdx.x * blockDim.x + threadIdx.x;
    if (i < NB * NC) g_pooled[i] = 0.0f;
    if (i < NB * NH) g_Z[i] = 0.0f;
}

// ============================================================
// K1: scores GEMM. CTA: 256 rows x 16 heads, 128 threads
// (64 rowg x 2 headg), thread tile 4 rows x 8 heads, f32x2 accums.
// DOUBLE-BUFFERED xs: one barrier per chunk; LDG(c+2) issued a full
// chunk of compute before its STS, hiding DRAM latency. fp16 scores.
// ============================================================
__global__ void __launch_bounds__(128, 2)
k_scores(const float* __restrict__ x, const float* __restrict__ q) {
    extern __shared__ float sm[];
    float* qs  = sm;                       // 16*1024 floats (64 KB)
    float* xs0 = sm + NH * NC;             // 256*20 floats (20 KB)
    float* xs1 = xs0 + TILE_R * XSTR;      // 20 KB
    __shared__ float zsh[NH];

    const int b = blockIdx.y, tile = blockIdx.x, tid = threadIdx.x;
    const int rowg = tid & 63, headg = tid >> 6;      // 64 x 2
    const int crow = tid >> 2, ccol = (tid & 3) * 4;  // copy: 4 lanes/row

    for (int i = tid; i < NH * NC / 4; i += 128)
        ((float4*)qs)[i] = ((const float4*)q)[i];
    if (tid < NH) zsh[tid] = 0.0f;

    const float* xb = x + ((size_t)(b * NT + tile * TILE_R)) * NC;

    float4 r[8];
#define LOADC(c)                                                            \
    _Pragma("unroll")                                                       \
    for (int g = 0; g < 8; g++)                                             \
        r[g] = *(const float4*)(xb + (size_t)(g * 32 + crow) * NC           \
                                + (c) * KC + ccol);
#define STORE(buf)                                                          \
    _Pragma("unroll")                                                       \
    for (int g = 0; g < 8; g++)                                             \
        *(float4*)((buf) + (g * 32 + crow) * XSTR + ccol) = r[g];

    LOADC(0);
    STORE(xs0);
    __syncthreads();
    LOADC(1);

    unsigned long long acc[4][8];
    #pragma unroll
    for (int m = 0; m < 4; m++)
        #pragma unroll
        for (int h = 0; h < 8; h++) acc[m][h] = 0ull;

    for (int c = 0; c < NCH; c++) {
        const float* cur = (c & 1) ? xs1 : xs0;
        float* nxt       = (c & 1) ? xs0 : xs1;

        const float* qc = qs + (size_t)headg * 8 * NC + c * KC;
        #pragma unroll
        for (int j = 0; j < 4; j++) {        // 4 channels per step
            ulonglong2 xv[4];
            #pragma unroll
            for (int m = 0; m < 4; m++)
                xv[m] = *(const ulonglong2*)(cur + (rowg + 64 * m) * XSTR + 4 * j);
            #pragma unroll
            for (int h = 0; h < 8; h++) {
                ulonglong2 qv = *(const ulonglong2*)(qc + h * NC + 4 * j); // broadcast
                #pragma unroll
                for (int m = 0; m < 4; m++) {
                    ffma2(acc[m][h], xv[m].x, qv.x);
                    ffma2(acc[m][h], xv[m].y, qv.y);
                }
            }
        }

        if (c + 1 < NCH) {
            STORE(nxt);                      // r holds chunk c+1
            __syncthreads();                 // publishes nxt; closes reads of cur
            if (c + 2 < NCH) { LOADC(c + 2); }
        }
    }
#undef LOADC
#undef STORE

    float zacc[8];
    #pragma unroll
    for (int h = 0; h < 8; h++) zacc[h] = 0.0f;

    #pragma unroll
    for (int m = 0; m < 4; m++) {
        int rr = tile * TILE_R + rowg + 64 * m;
        float s[8];
        #pragma unroll
        for (int h = 0; h < 8; h++) {
            s[h] = (lo2(acc[m][h]) + hi2(acc[m][h])) * SCALE;
            zacc[h] += expf(s[h]);
        }
        HPack pk;
        pk.h2[0] = __floats2half2_rn(s[0], s[1]);
        pk.h2[1] = __floats2half2_rn(s[2], s[3]);
        pk.h2[2] = __floats2half2_rn(s[4], s[5]);
        pk.h2[3] = __floats2half2_rn(s[6], s[7]);
        *(uint4*)(g_scoresh + ((size_t)b * NT + rr) * NH + headg * 8) = pk.u;
    }
    #pragma unroll
    for (int h = 0; h < 8; h++) {
        float v = zacc[h];
        #pragma unroll
        for (int m2 = 16; m2 >= 1; m2 >>= 1)
            v += __shfl_xor_sync(0xffffffffu, v, m2);
        if ((tid & 31) == 0) atomicAdd(&zsh[headg * 8 + h], v);
    }
    __syncthreads();
    if (tid < NH) atomicAdd(&g_Z[b * NH + tid], zsh[tid]);
}

// ============================================================
// K2: pooled[b,c] += sum_t w[b,t]*x[b,t,c],  w = (1/16) sum_h exp(s)/Z_h
// ============================================================
__global__ void __launch_bounds__(256)
k_pool(const float* __restrict__ x) {
    __shared__ float ws[128];
    __shared__ float rz[16];
    const int b = blockIdx.y, tile = blockIdx.x, tid = threadIdx.x;

    if (tid < 16) rz[tid] = 1.0f / g_Z[b * NH + tid];
    __syncthreads();

    if (tid < 128) {
        const int r = tile * 128 + tid;
        HPack pk;
        pk.u = *(const uint4*)(g_scoresh + ((size_t)b * NT + r) * NH);
        float w = 0.0f;
        #pragma unroll
        for (int k = 0; k < 4; k++) {
            float2 f = __half22float2(pk.h2[k]);
            w += expf(f.x) * rz[2 * k] + expf(f.y) * rz[2 * k + 1];
        }
        HPack pk2;
        pk2.u = *(const uint4*)(g_scoresh + ((size_t)b * NT + r) * NH + 8);
        #pragma unroll
        for (int k = 0; k < 4; k++) {
            float2 f = __half22float2(pk2.h2[k]);
            w += expf(f.x) * rz[8 + 2 * k] + expf(f.y) * rz[8 + 2 * k + 1];
        }
        ws[tid] = w * (1.0f / 16.0f);
    }
    __syncthreads();

    const int c = tid * 4;
    float4 a0 = make_float4(0.f, 0.f, 0.f, 0.f);
    float4 a1 = make_float4(0.f, 0.f, 0.f, 0.f);
    const float* xb = x + ((size_t)b * NT + tile * 128) * NC + c;
    #pragma unroll 4
    for (int r = 0; r < 128; r += 2) {
        float4 x0 = *(const float4*)(xb + (size_t)r * NC);
        float4 x1 = *(const float4*)(xb + (size_t)(r + 1) * NC);
        float w0 = ws[r], w1 = ws[r + 1];
        a0.x += w0 * x0.x; a0.y += w0 * x0.y; a0.z += w0 * x0.z; a0.w += w0 * x0.w;
        a1.x += w1 * x1.x; a1.y += w1 * x1.y; a1.z += w1 * x1.z; a1.w += w1 * x1.w;
    }
    float* pp = g_pooled + b * NC + c;
    atomicAdd(pp + 0, a0.x + a1.x);
    atomicAdd(pp + 1, a0.y + a1.y);
    atomicAdd(pp + 2, a0.z + a1.z);
    atomicAdd(pp + 3, a0.w + a1.w);
}

// ============================================================
// K3: out[b,j] = <pooled[b,:], W[j,:]> + bias[j]
// ============================================================
__global__ void __launch_bounds__(256)
k_proj(const float* __restrict__ w, const float* __restrict__ bias,
       float* __restrict__ out) {
    const int warp = threadIdx.x >> 5, lane = threadIdx.x & 31;
    const int j = blockIdx.x * 8 + warp;

    float4 wr[8];
    const float4* wp = (const float4*)(w + (size_t)j * NC);
    #pragma unroll
    for (int i = 0; i < 8; i++) wr[i] = wp[lane + 32 * i];
    const float bj = bias[j];

    const int b0 = blockIdx.y * 8;
    for (int b = b0; b < b0 + 8; b++) {
        const float4* pp = (const float4*)(g_pooled + b * NC);
        float acc = 0.0f;
        #pragma unroll
        for (int i = 0; i < 8; i++) {
            float4 pv = pp[lane + 32 * i];
            acc += pv.x * wr[i].x + pv.y * wr[i].y
                 + pv.z * wr[i].z + pv.w * wr[i].w;
        }
        #pragma unroll
        for (int m = 16; m >= 1; m >>= 1)
            acc += __shfl_xor_sync(0xffffffffu, acc, m);
        if (lane == 0) out[b * NC + j] = acc + bj;
    }
}

// ============================================================
extern "C" void kernel_launch(void* const* d_in, const int* in_sizes, int n_in,
                              void* d_out, int out_size) {
    const float* x  = (const float*)d_in[0];
    const float* q  = (const float*)d_in[1];
    const float* pw = (const float*)d_in[2];
    const float* pb = (const float*)d_in[3];
    float* out      = (float*)d_out;

    const int smem = (NH * NC + 2 * TILE_R * XSTR) * (int)sizeof(float);  // 104 KB
    cudaFuncSetAttribute(k_scores, cudaFuncAttributeMaxDynamicSharedMemorySize, smem);

    k_zero<<<128, 256>>>();
    k_scores<<<dim3(NT / TILE_R, NB), 128, smem>>>(x, q);
    k_pool<<<dim3(64, NB), 256>>>(x);
    k_proj<<<dim3(128, 4), 256>>>(pw, pb, out);
}

// round 17
// speedup vs baseline: 1.6565x; 1.0350x over previous
#include <cuda_runtime.h>
#include <cuda_fp16.h>

#define NB 32
#define NT 8192
#define NC 1024
#define NH 16
#define SCALE 0.03125f   // 1024^-0.5

#define TILE_R 256
#define KC 16
#define XSTR 20                  // 16 + 4 pad: conflict-free B-fragment LDS
#define NCH (NC / KC)            // 64 chunks

// ---- scratch ----
__device__ __align__(16) __half g_scoresh[(size_t)NB * NH * NT];  // TRANSPOSED [b][h][t]
__device__ float    g_Z[NB * NH];
__device__ float    g_pooled[NB * NC];
__device__ unsigned g_qTt[NC * NH];       // qT[ch][h], tf32 bits

__device__ __forceinline__ void mma_tf32(float* d, const unsigned* a,
                                         unsigned b0, unsigned b1) {
    asm volatile(
        "mma.sync.aligned.m16n8k8.row.col.f32.tf32.tf32.f32 "
        "{%0,%1,%2,%3}, {%4,%5,%6,%7}, {%8,%9}, {%0,%1,%2,%3};"
        : "+f"(d[0]), "+f"(d[1]), "+f"(d[2]), "+f"(d[3])
        : "r"(a[0]), "r"(a[1]), "r"(a[2]), "r"(a[3]), "r"(b0), "r"(b1));
}
__device__ __forceinline__ unsigned to_tf32(float f) {
    unsigned u;
    asm("cvt.rna.tf32.f32 %0, %1;" : "=r"(u) : "f"(f));
    return u;
}

// ============================================================
// K0: zero accumulators + build tf32 qT[ch][h]
// ============================================================
__global__ void k_zero(const float* __restrict__ q) {
    int i = blockIdx.x * blockDim.x + threadIdx.x;
    if (i < NB * NC) g_pooled[i] = 0.0f;
    if (i < NB * NH) g_Z[i] = 0.0f;
    if (i < NC * NH) {
        int ch = i >> 4, h = i & 15;
        g_qTt[i] = to_tf32(q[h * NC + ch]);
    }
}

// ============================================================
// K1: scores GEMM on tensor cores (mma.m16n8k8.tf32).
// M=16 -> heads, N=8 -> x-rows, K=8 -> channels.
// CTA: 128 threads (4 warps) x 256 rows; warp owns 64 rows (8 n8-groups).
// A frag = q (smem, tf32 bits, loaded once per chunk, amortized x8).
// B frag = x (smem staged LDG->STS, conflict-free LDS.32 + cvt).
// D accumulates in regs across all 64 chunks (8 groups x 4 f32).
// Scores written fp16 TRANSPOSED [b][h][t] via half2.
// ============================================================
__global__ void __launch_bounds__(128, 2)
k_scores(const float* __restrict__ x) {
    extern __shared__ float sm[];
    unsigned* qts = (unsigned*)sm;          // NC*16 u32 (64 KB)
    float* xs0 = sm + NC * NH;              // 256*20 floats (20 KB)
    float* xs1 = xs0 + TILE_R * XSTR;       // 20 KB
    __shared__ float zsh[NH];

    const int b = blockIdx.y, tile = blockIdx.x, tid = threadIdx.x;
    const int warp = tid >> 5, lane = tid & 31;
    const int gid = lane >> 2, tg = lane & 3;         // mma group/thread ids
    const int crow = tid >> 2, ccol = (tid & 3) * 4;  // staging: 4 lanes/row

    for (int i = tid; i < NC * NH / 4; i += 128)
        ((uint4*)qts)[i] = ((const uint4*)g_qTt)[i];
    if (tid < NH) zsh[tid] = 0.0f;

    const float* xb = x + ((size_t)(b * NT + tile * TILE_R)) * NC;

    float4 r[8];
#define LOADC(c)                                                            \
    _Pragma("unroll")                                                       \
    for (int g = 0; g < 8; g++)                                             \
        r[g] = *(const float4*)(xb + (size_t)(g * 32 + crow) * NC           \
                                + (c) * KC + ccol);
#define STORE(buf)                                                          \
    _Pragma("unroll")                                                       \
    for (int g = 0; g < 8; g++)                                             \
        *(float4*)((buf) + (g * 32 + crow) * XSTR + ccol) = r[g];

    LOADC(0);
    STORE(xs0);
    __syncthreads();
    LOADC(1);

    float d[8][4];
    #pragma unroll
    for (int g = 0; g < 8; g++)
        #pragma unroll
        for (int k = 0; k < 4; k++) d[g][k] = 0.0f;

    for (int c = 0; c < NCH; c++) {
        const float* cur = (c & 1) ? xs1 : xs0;
        float* nxt       = (c & 1) ? xs0 : xs1;

        // A fragments (q) for the chunk's two k-steps
        unsigned a[2][4];
        #pragma unroll
        for (int ks = 0; ks < 2; ks++) {
            const unsigned* qp = qts + (c * KC + ks * 8 + tg) * NH;
            a[ks][0] = qp[gid];
            a[ks][1] = qp[gid + 8];
            a[ks][2] = qp[4 * NH + gid];
            a[ks][3] = qp[4 * NH + gid + 8];
        }

        const float* xw = cur + (64 * warp + gid) * XSTR;
        #pragma unroll
        for (int g = 0; g < 8; g++) {
            const float* xr = xw + g * 8 * XSTR;
            #pragma unroll
            for (int ks = 0; ks < 2; ks++) {
                unsigned b0 = to_tf32(xr[ks * 8 + tg]);
                unsigned b1 = to_tf32(xr[ks * 8 + tg + 4]);
                mma_tf32(d[g], a[ks], b0, b1);
            }
        }

        if (c + 1 < NCH) {
            STORE(nxt);                      // r holds chunk c+1
            __syncthreads();                 // publish nxt; close reads of cur
            if (c + 2 < NCH) { LOADC(c + 2); }
        }
    }
#undef LOADC
#undef STORE

    // Epilogue: thread holds heads {gid, gid+8} x rows {2tg, 2tg+1} per group.
    float zlo = 0.0f, zhi = 0.0f;
    #pragma unroll
    for (int g = 0; g < 8; g++) {
        const int R = tile * TILE_R + 64 * warp + 8 * g + 2 * tg;
        float s0 = d[g][0] * SCALE, s1 = d[g][1] * SCALE;
        float s2 = d[g][2] * SCALE, s3 = d[g][3] * SCALE;
        *(__half2*)(g_scoresh + ((size_t)b * NH + gid) * NT + R) =
            __floats2half2_rn(s0, s1);
        *(__half2*)(g_scoresh + ((size_t)b * NH + gid + 8) * NT + R) =
            __floats2half2_rn(s2, s3);
        zlo += expf(s0) + expf(s1);
        zhi += expf(s2) + expf(s3);
    }
    zlo += __shfl_xor_sync(0xffffffffu, zlo, 1);
    zlo += __shfl_xor_sync(0xffffffffu, zlo, 2);
    zhi += __shfl_xor_sync(0xffffffffu, zhi, 1);
    zhi += __shfl_xor_sync(0xffffffffu, zhi, 2);
    if (tg == 0) {
        atomicAdd(&zsh[gid], zlo);
        atomicAdd(&zsh[gid + 8], zhi);
    }
    __syncthreads();
    if (tid < NH) atomicAdd(&g_Z[b * NH + tid], zsh[tid]);
}

// ============================================================
// K2: pooled[b,c] += sum_t w[b,t]*x[b,t,c],  w = (1/16) sum_h exp(s)/Z_h
// scores read from TRANSPOSED fp16 layout (coalesced per head).
// ============================================================
__global__ void __launch_bounds__(256)
k_pool(const float* __restrict__ x) {
    __shared__ float ws[128];
    __shared__ float rz[16];
    const int b = blockIdx.y, tile = blockIdx.x, tid = threadIdx.x;

    if (tid < 16) rz[tid] = 1.0f / g_Z[b * NH + tid];
    __syncthreads();

    if (tid < 128) {
        const int r = tile * 128 + tid;
        float w = 0.0f;
        #pragma unroll
        for (int h = 0; h < NH; h++) {
            float s = __half2float(g_scoresh[((size_t)b * NH + h) * NT + r]);
            w += expf(s) * rz[h];
        }
        ws[tid] = w * (1.0f / 16.0f);
    }
    __syncthreads();

    const int c = tid * 4;
    float4 a0 = make_float4(0.f, 0.f, 0.f, 0.f);
    float4 a1 = make_float4(0.f, 0.f, 0.f, 0.f);
    const float* xb = x + ((size_t)b * NT + tile * 128) * NC + c;
    #pragma unroll 4
    for (int r = 0; r < 128; r += 2) {
        float4 x0 = *(const float4*)(xb + (size_t)r * NC);
        float4 x1 = *(const float4*)(xb + (size_t)(r + 1) * NC);
        float w0 = ws[r], w1 = ws[r + 1];
        a0.x += w0 * x0.x; a0.y += w0 * x0.y; a0.z += w0 * x0.z; a0.w += w0 * x0.w;
        a1.x += w1 * x1.x; a1.y += w1 * x1.y; a1.z += w1 * x1.z; a1.w += w1 * x1.w;
    }
    float* pp = g_pooled + b * NC + c;
    atomicAdd(pp + 0, a0.x + a1.x);
    atomicAdd(pp + 1, a0.y + a1.y);
    atomicAdd(pp + 2, a0.z + a1.z);
    atomicAdd(pp + 3, a0.w + a1.w);
}

// ============================================================
// K3: out[b,j] = <pooled[b,:], W[j,:]> + bias[j]
// ============================================================
__global__ void __launch_bounds__(256)
k_proj(const float* __restrict__ w, const float* __restrict__ bias,
       float* __restrict__ out) {
    const int warp = threadIdx.x >> 5, lane = threadIdx.x & 31;
    const int j = blockIdx.x * 8 + warp;

    float4 wr[8];
    const float4* wp = (const float4*)(w + (size_t)j * NC);
    #pragma unroll
    for (int i = 0; i < 8; i++) wr[i] = wp[lane + 32 * i];
    const float bj = bias[j];

    const int b0 = blockIdx.y * 8;
    for (int b = b0; b < b0 + 8; b++) {
        const float4* pp = (const float4*)(g_pooled + b * NC);
        float acc = 0.0f;
        #pragma unroll
        for (int i = 0; i < 8; i++) {
            float4 pv = pp[lane + 32 * i];
            acc += pv.x * wr[i].x + pv.y * wr[i].y
                 + pv.z * wr[i].z + pv.w * wr[i].w;
        }
        #pragma unroll
        for (int m = 16; m >= 1; m >>= 1)
            acc += __shfl_xor_sync(0xffffffffu, acc, m);
        if (lane == 0) out[b * NC + j] = acc + bj;
    }
}

// ============================================================
extern "C" void kernel_launch(void* const* d_in, const int* in_sizes, int n_in,
                              void* d_out, int out_size) {
    const float* x  = (const float*)d_in[0];
    const float* q  = (const float*)d_in[1];
    const float* pw = (const float*)d_in[2];
    const float* pb = (const float*)d_in[3];
    float* out      = (float*)d_out;

    const int smem = (NC * NH + 2 * TILE_R * XSTR) * (int)sizeof(float);  // 104 KB
    cudaFuncSetAttribute(k_scores, cudaFuncAttributeMaxDynamicSharedMemorySize, smem);

    k_zero<<<128, 256>>>(q);
    k_scores<<<dim3(NT / TILE_R, NB), 128, smem>>>(x);
    k_pool<<<dim3(64, NB), 256>>>(x);
    k_proj<<<dim3(128, 4), 256>>>(pw, pb, out);
}